// round 13
// baseline (speedup 1.0000x reference)
#include <cuda_runtime.h>

#define BATCH    16
#define NTUP     65536
#define IN_SIZE  4096
#define OUT_SIZE 4096
#define TPB      1024
#define CPB      18                      // CTAs per batch
#define GRID_MAIN (BATCH * CPB)          // 288 <= 296 resident: one wave

__global__ __launch_bounds__(TPB, 2)
void hyper_main_kernel(const float*  __restrict__ x,
                       const float2* __restrict__ means,
                       const float*  __restrict__ sigmas,
                       const float*  __restrict__ values,
                       const float4* __restrict__ noise,
                       const float*  __restrict__ bias,
                       float* __restrict__ y) {
    __shared__ float sx[IN_SIZE];
    __shared__ float sy[OUT_SIZE];   // per-CTA private accumulator

    const int b = blockIdx.x & 15;   // batch
    const int r = blockIdx.x >> 4;   // rank within batch (0..17)

    // stage x[b] into shared + zero the private accumulator (1 iter/thread)
    {
        const float4* xb4 = reinterpret_cast<const float4*>(x + b * IN_SIZE);
        float4* sx4 = reinterpret_cast<float4*>(sx);
        float4* sy4 = reinterpret_cast<float4*>(sy);
        const float4 z = make_float4(0.f, 0.f, 0.f, 0.f);
        #pragma unroll
        for (int i = threadIdx.x; i < IN_SIZE / 4; i += TPB) {
            sx4[i] = xb4[i];
            sy4[i] = z;
        }
    }
    __syncthreads();

    // two adjacent lanes share one tuple; each lane owns 4 of the 8 samples
    const int h      = threadIdx.x & 1;          // half selector
    const int bn0    = b * NTUP;
    const int stride = CPB * (TPB / 2);

    for (int t = r * (TPB / 2) + (threadIdx.x >> 1); t < NTUP; t += stride) {
        const int bn = bn0 + t;

        const float2 mu  = means[bn];    // pair-duplicated, sector-shared
        const float  sg  = sigmas[bn];
        const float  val = values[bn];

        // this lane's 8 noise floats (consecutive tids -> contiguous float4s)
        const float4 nza = noise[bn * 4 + 2 * h + 0];
        const float4 nzb = noise[bn * 4 + 2 * h + 1];
        const float nr[8] = { nza.x, nza.y, nza.z, nza.w,
                              nzb.x, nzb.y, nzb.z, nzb.w };

        // probs: sigma and the 2*pi*s2 denominator cancel in the
        // D-normalization, so probs depend only on the noise.
        float p[4];
        float psum = 0.0f;
        #pragma unroll
        for (int d = 0; d < 4; d++) {
            const float a = nr[2 * d + 0];
            const float c = nr[2 * d + 1];
            p[d] = __expf(-0.5f * (a * a + c * c));
            psum += p[d];
        }
        // combine the two half-sums across the lane pair
        psum += __shfl_xor_sync(0xffffffffu, psum, 1);
        const float scale = __fdividef(val, psum);

        // 4 samples: address math + gather
        int   oi[4];
        float contrib[4];
        #pragma unroll
        for (int d = 0; d < 4; d++) {
            const float s0 = fmaf(nr[2 * d + 0], sg, mu.x);
            const float s1 = fmaf(nr[2 * d + 1], sg, mu.y);
            float f0 = rintf(s0);   // round-half-even == jnp.round
            float f1 = rintf(s1);
            f0 = fminf(fmaxf(f0, 0.0f), (float)(OUT_SIZE - 1));
            f1 = fminf(fmaxf(f1, 0.0f), (float)(IN_SIZE - 1));
            oi[d] = (int)f0;
            contrib[d] = (scale * p[d]) * sx[(int)f1];
        }

        // merge samples sharing an output row (within this lane's half)
        #pragma unroll
        for (int d = 1; d < 4; d++) {
            const float cd = contrib[d];
            bool merged = false;
            #pragma unroll
            for (int j = 0; j < d; j++) {
                const bool eq = (!merged) && (oi[d] == oi[j]);
                if (eq) contrib[j] += cd;
                merged = merged || eq;
            }
            if (merged) oi[d] = -1;
        }

        #pragma unroll
        for (int d = 0; d < 4; d++) {
            if (oi[d] >= 0)
                atomicAdd(&sy[oi[d]], contrib[d]);
        }
    }

    __syncthreads();

    // coalesced, vectorized flush (1 iter/thread); rank-0 adds the bias
    {
        const float4* sy4 = reinterpret_cast<const float4*>(sy);
        const float4* bias4 = reinterpret_cast<const float4*>(bias);
        float4* yb4 = reinterpret_cast<float4*>(y + b * OUT_SIZE);
        #pragma unroll
        for (int i = threadIdx.x; i < OUT_SIZE / 4; i += TPB) {
            float4 v = sy4[i];
            if (r == 0) {
                const float4 bv = bias4[i];
                v.x += bv.x; v.y += bv.y; v.z += bv.z; v.w += bv.w;
            }
            asm volatile("red.global.add.v4.f32 [%0], {%1, %2, %3, %4};"
                         :: "l"(yb4 + i), "f"(v.x), "f"(v.y), "f"(v.z), "f"(v.w)
                         : "memory");
        }
    }
}

extern "C" void kernel_launch(void* const* d_in, const int* in_sizes, int n_in,
                              void* d_out, int out_size) {
    const float*  x      = (const float*) d_in[0];  // [16, 4096]
    const float2* means  = (const float2*)d_in[1];  // [16, 65536, 2]
    const float*  sigmas = (const float*) d_in[2];  // [16, 65536]
    const float*  values = (const float*) d_in[3];  // [16, 65536]
    const float*  bias   = (const float*) d_in[4];  // [4096]
    const float4* noise  = (const float4*)d_in[5];  // [16, 65536, 8, 2]
    float* y = (float*)d_out;                       // [16, 4096]

    // zero the (poisoned) output; bias is added by the rank-0 CTAs' flush
    cudaMemsetAsync(y, 0, (size_t)BATCH * OUT_SIZE * sizeof(float));

    hyper_main_kernel<<<GRID_MAIN, TPB>>>(x, means, sigmas, values, noise,
                                          bias, y);
}

// round 14
// speedup vs baseline: 1.0079x; 1.0079x over previous
#include <cuda_runtime.h>

#define BATCH    16
#define NTUP     65536
#define IN_SIZE  4096
#define OUT_SIZE 4096
#define TPB      512
#define CPB      37                      // CTAs per batch
#define GRID_MAIN (BATCH * CPB)          // 592 = 148 SMs x 4 CTAs: one wave

// y[b*OUT_SIZE + o] = bias[o], vectorized float4
__global__ void hyper_init_kernel(const float4* __restrict__ bias4,
                                  float4* __restrict__ y4) {
    const int i = blockIdx.x * blockDim.x + threadIdx.x;   // 0 .. 16K-1
    y4[i] = bias4[i & (OUT_SIZE / 4 - 1)];
}

__global__ __launch_bounds__(TPB, 4)
void hyper_main_kernel(const float*  __restrict__ x,
                       const float2* __restrict__ means,
                       const float*  __restrict__ sigmas,
                       const float*  __restrict__ values,
                       const float4* __restrict__ noise,
                       float* __restrict__ y) {
    __shared__ float sx[IN_SIZE];
    __shared__ float sy[OUT_SIZE];   // per-CTA private accumulator

    const int b = blockIdx.x & 15;   // batch
    const int r = blockIdx.x >> 4;   // rank within batch (0..36)

    // stage x[b] into shared + zero the private accumulator
    {
        const float4* xb4 = reinterpret_cast<const float4*>(x + b * IN_SIZE);
        float4* sx4 = reinterpret_cast<float4*>(sx);
        float4* sy4 = reinterpret_cast<float4*>(sy);
        const float4 z = make_float4(0.f, 0.f, 0.f, 0.f);
        #pragma unroll
        for (int i = threadIdx.x; i < IN_SIZE / 4; i += TPB) {
            sx4[i] = xb4[i];
            sy4[i] = z;
        }
    }
    __syncthreads();

    // two adjacent lanes share one tuple; each lane owns 4 of the 8 samples
    const int h      = threadIdx.x & 1;          // half selector
    const int bn0    = b * NTUP;
    const int stride = CPB * (TPB / 2);

    for (int t = r * (TPB / 2) + (threadIdx.x >> 1); t < NTUP; t += stride) {
        const int bn = bn0 + t;

        const float2 mu  = means[bn];    // pair-duplicated, sector-shared
        const float  sg  = sigmas[bn];
        const float  val = values[bn];

        // this lane's 8 noise floats (consecutive tids -> contiguous float4s)
        const float4 nza = noise[bn * 4 + 2 * h + 0];
        const float4 nzb = noise[bn * 4 + 2 * h + 1];
        const float nr[8] = { nza.x, nza.y, nza.z, nza.w,
                              nzb.x, nzb.y, nzb.z, nzb.w };

        // probs: sigma and the 2*pi*s2 denominator cancel in the
        // D-normalization, so probs depend only on the noise.
        float p[4];
        float psum = 0.0f;
        #pragma unroll
        for (int d = 0; d < 4; d++) {
            const float a = nr[2 * d + 0];
            const float c = nr[2 * d + 1];
            p[d] = __expf(-0.5f * (a * a + c * c));
            psum += p[d];
        }
        // combine the two half-sums across the lane pair
        psum += __shfl_xor_sync(0xffffffffu, psum, 1);
        const float scale = __fdividef(val, psum);

        // 4 samples: address math + gather
        int   oi[4];
        float contrib[4];
        #pragma unroll
        for (int d = 0; d < 4; d++) {
            const float s0 = fmaf(nr[2 * d + 0], sg, mu.x);
            const float s1 = fmaf(nr[2 * d + 1], sg, mu.y);
            float f0 = rintf(s0);   // round-half-even == jnp.round
            float f1 = rintf(s1);
            f0 = fminf(fmaxf(f0, 0.0f), (float)(OUT_SIZE - 1));
            f1 = fminf(fmaxf(f1, 0.0f), (float)(IN_SIZE - 1));
            oi[d] = (int)f0;
            contrib[d] = (scale * p[d]) * sx[(int)f1];
        }

        // merge samples sharing an output row (within this lane's half)
        #pragma unroll
        for (int d = 1; d < 4; d++) {
            const float cd = contrib[d];
            bool merged = false;
            #pragma unroll
            for (int j = 0; j < d; j++) {
                const bool eq = (!merged) && (oi[d] == oi[j]);
                if (eq) contrib[j] += cd;
                merged = merged || eq;
            }
            if (merged) oi[d] = -1;
        }

        #pragma unroll
        for (int d = 0; d < 4; d++) {
            if (oi[d] >= 0)
                atomicAdd(&sy[oi[d]], contrib[d]);
        }
    }

    __syncthreads();

    // coalesced, vectorized flush of the private accumulator into global y
    {
        const float4* sy4 = reinterpret_cast<const float4*>(sy);
        float4* yb4 = reinterpret_cast<float4*>(y + b * OUT_SIZE);
        #pragma unroll
        for (int i = threadIdx.x; i < OUT_SIZE / 4; i += TPB) {
            const float4 v = sy4[i];
            asm volatile("red.global.add.v4.f32 [%0], {%1, %2, %3, %4};"
                         :: "l"(yb4 + i), "f"(v.x), "f"(v.y), "f"(v.z), "f"(v.w)
                         : "memory");
        }
    }
}

extern "C" void kernel_launch(void* const* d_in, const int* in_sizes, int n_in,
                              void* d_out, int out_size) {
    const float*  x      = (const float*) d_in[0];  // [16, 4096]
    const float2* means  = (const float2*)d_in[1];  // [16, 65536, 2]
    const float*  sigmas = (const float*) d_in[2];  // [16, 65536]
    const float*  values = (const float*) d_in[3];  // [16, 65536]
    const float*  bias   = (const float*) d_in[4];  // [4096]
    const float4* noise  = (const float4*)d_in[5];  // [16, 65536, 8, 2]
    float* y = (float*)d_out;                       // [16, 4096]

    // seed y with the bias (d_out is poisoned before timing)
    hyper_init_kernel<<<64, 256>>>((const float4*)bias, (float4*)y);

    hyper_main_kernel<<<GRID_MAIN, TPB>>>(x, means, sigmas, values, noise, y);
}

// round 15
// speedup vs baseline: 1.0182x; 1.0103x over previous
#include <cuda_runtime.h>

#define BATCH    16
#define NTUP     65536
#define IN_SIZE  4096
#define OUT_SIZE 4096
#define TPB      512
#define CPB      37                      // CTAs per batch
#define GRID_MAIN (BATCH * CPB)          // 592 = 148 SMs x 4 CTAs: one wave

// y[b*OUT_SIZE + o] = bias[o]
__global__ void hyper_init_kernel(const float* __restrict__ bias,
                                  float* __restrict__ y) {
    int i = blockIdx.x * blockDim.x + threadIdx.x;
    if (i < BATCH * OUT_SIZE) y[i] = bias[i & (OUT_SIZE - 1)];
}

__global__ __launch_bounds__(TPB, 4)
void hyper_main_kernel(const float*  __restrict__ x,
                       const float2* __restrict__ means,
                       const float*  __restrict__ sigmas,
                       const float*  __restrict__ values,
                       const float4* __restrict__ noise,
                       float* __restrict__ y) {
    __shared__ float sx[IN_SIZE];
    __shared__ float sy[OUT_SIZE];   // per-CTA private accumulator

    const int b = blockIdx.x & 15;   // batch
    const int r = blockIdx.x >> 4;   // rank within batch (0..36)

    // stage x[b] into shared + zero the private accumulator
    {
        const float4* xb4 = reinterpret_cast<const float4*>(x + b * IN_SIZE);
        float4* sx4 = reinterpret_cast<float4*>(sx);
        float4* sy4 = reinterpret_cast<float4*>(sy);
        const float4 z = make_float4(0.f, 0.f, 0.f, 0.f);
        #pragma unroll
        for (int i = threadIdx.x; i < IN_SIZE / 4; i += TPB) {
            sx4[i] = xb4[i];
            sy4[i] = z;
        }
    }
    __syncthreads();

    // two adjacent lanes share one tuple; each lane owns 4 of the 8 samples
    const int h      = threadIdx.x & 1;          // half selector
    const int bn0    = b * NTUP;
    const int stride = CPB * (TPB / 2);

    for (int t = r * (TPB / 2) + (threadIdx.x >> 1); t < NTUP; t += stride) {
        const int bn = bn0 + t;

        const float2 mu  = means[bn];    // pair-duplicated, sector-shared
        const float  sg  = sigmas[bn];
        const float  val = values[bn];

        // this lane's 8 noise floats (consecutive tids -> contiguous float4s)
        const float4 nza = noise[bn * 4 + 2 * h + 0];
        const float4 nzb = noise[bn * 4 + 2 * h + 1];
        const float nr[8] = { nza.x, nza.y, nza.z, nza.w,
                              nzb.x, nzb.y, nzb.z, nzb.w };

        // probs: sigma and the 2*pi*s2 denominator cancel in the
        // D-normalization, so probs depend only on the noise.
        float p[4];
        float psum = 0.0f;
        #pragma unroll
        for (int d = 0; d < 4; d++) {
            const float a = nr[2 * d + 0];
            const float c = nr[2 * d + 1];
            p[d] = __expf(-0.5f * (a * a + c * c));
            psum += p[d];
        }
        // combine the two half-sums across the lane pair
        psum += __shfl_xor_sync(0xffffffffu, psum, 1);
        const float scale = __fdividef(val, psum);

        // 4 samples: address math + gather
        int   oi[4];
        float contrib[4];
        #pragma unroll
        for (int d = 0; d < 4; d++) {
            const float s0 = fmaf(nr[2 * d + 0], sg, mu.x);
            const float s1 = fmaf(nr[2 * d + 1], sg, mu.y);
            float f0 = rintf(s0);   // round-half-even == jnp.round
            float f1 = rintf(s1);
            f0 = fminf(fmaxf(f0, 0.0f), (float)(OUT_SIZE - 1));
            f1 = fminf(fmaxf(f1, 0.0f), (float)(IN_SIZE - 1));
            oi[d] = (int)f0;
            contrib[d] = (scale * p[d]) * sx[(int)f1];
        }

        // merge samples sharing an output row (within this lane's half)
        #pragma unroll
        for (int d = 1; d < 4; d++) {
            const float cd = contrib[d];
            bool merged = false;
            #pragma unroll
            for (int j = 0; j < d; j++) {
                const bool eq = (!merged) && (oi[d] == oi[j]);
                if (eq) contrib[j] += cd;
                merged = merged || eq;
            }
            if (merged) oi[d] = -1;
        }

        #pragma unroll
        for (int d = 0; d < 4; d++) {
            if (oi[d] >= 0)
                atomicAdd(&sy[oi[d]], contrib[d]);
        }
    }

    __syncthreads();

    // coalesced, vectorized flush of the private accumulator into global y
    {
        const float4* sy4 = reinterpret_cast<const float4*>(sy);
        float4* yb4 = reinterpret_cast<float4*>(y + b * OUT_SIZE);
        #pragma unroll
        for (int i = threadIdx.x; i < OUT_SIZE / 4; i += TPB) {
            const float4 v = sy4[i];
            asm volatile("red.global.add.v4.f32 [%0], {%1, %2, %3, %4};"
                         :: "l"(yb4 + i), "f"(v.x), "f"(v.y), "f"(v.z), "f"(v.w)
                         : "memory");
        }
    }
}

extern "C" void kernel_launch(void* const* d_in, const int* in_sizes, int n_in,
                              void* d_out, int out_size) {
    const float*  x      = (const float*) d_in[0];  // [16, 4096]
    const float2* means  = (const float2*)d_in[1];  // [16, 65536, 2]
    const float*  sigmas = (const float*) d_in[2];  // [16, 65536]
    const float*  values = (const float*) d_in[3];  // [16, 65536]
    const float*  bias   = (const float*) d_in[4];  // [4096]
    const float4* noise  = (const float4*)d_in[5];  // [16, 65536, 8, 2]
    float* y = (float*)d_out;                       // [16, 4096]

    // seed y with the bias (d_out is poisoned before timing)
    hyper_init_kernel<<<(BATCH * OUT_SIZE + 255) / 256, 256>>>(bias, y);

    hyper_main_kernel<<<GRID_MAIN, TPB>>>(x, means, sigmas, values, noise, y);
}